// round 16
// baseline (speedup 1.0000x reference)
#include <cuda_runtime.h>
#include <cuda_fp16.h>
#include <cstdint>
#include <math.h>

// ---------------------------------------------------------------------------
// SelfAttention via split-fp16 HMMA (mma.sync m16n8k16.f32.f16.f16.f32).
// out = softmax((x Wq^T * 0.06)(x Wk^T)^T)*dropmask @ (x Wv^T) @ Wo^T
// N = 8192, M = 1024.
// Precision scheme (calibrated R8..R15):
//   - A operands always fp16 hi-only.
//   - Projections (Wk,Wq,Wv): B split hi+lo, 2 passes (must stay split).
//   - QK^T, S@V, out GEMM: single-pass. Measured error budget ~5.2e-4.
// R16 = R15 + (a) out GEMM single-pass, (b) early-barrier reorder in the
//       mainloop (sync after cheap LDSM instead of after the MMA burst),
//       (c) 512-thread softmax.
// ---------------------------------------------------------------------------

#define NF 8192
#define MF 1024

// ---------------- scratch (__device__ globals) ------------------------------
__device__ float  g_S [(size_t)NF * NF];                 // 256 MB logits
__device__ __half g_Sh[(size_t)NF * NF];                 // 128 MB (A side)
__device__ __half g_xh[(size_t)NF * MF];
__device__ __half g_Wkh[(size_t)MF * MF], g_Wkl[(size_t)MF * MF];
__device__ __half g_Wqh[(size_t)MF * MF], g_Wql[(size_t)MF * MF];
__device__ __half g_Wvh[(size_t)MF * MF], g_Wvl[(size_t)MF * MF];
__device__ __half g_Woh[(size_t)MF * MF];                // Wo hi only
__device__ __half g_Kh[(size_t)NF * MF];                 // K hi only
__device__ __half g_Qh[(size_t)NF * MF];
__device__ __half g_Vth[(size_t)MF * NF];                // V^T hi only
__device__ __half g_Yh[(size_t)NF * MF];

// ---------------- tile config ----------------------------------------------
#define BM 128
#define BN 64
#define BKE 32                    // K elems per chunk (fp16)
#define RS 40                     // smem row stride in elems (80 B)
#define OFF_A  0                          // A: 128 rows x 80B = 10240
#define OFF_BH (BM * RS * 2)              // Bh: 64 rows x 80B = 5120
#define OFF_BL (BM * RS * 2 + BN * RS * 2)
#define STAGE_B ((BM + 2 * BN) * RS * 2)  // 20480
#define NSTAGE 3
#define DYN_SMEM (NSTAGE * STAGE_B)       // 61440/CTA (3 CTAs -> 180 KB/SM)

// ---------------- PTX helpers ----------------------------------------------
__device__ __forceinline__ uint32_t s2u(const void* p) {
    uint32_t a;
    asm("{ .reg .u64 t; cvta.to.shared.u64 t, %1; cvt.u32.u64 %0, t; }"
        : "=r"(a) : "l"(p));
    return a;
}
__device__ __forceinline__ void cpa16(uint32_t dst, const void* src) {
    asm volatile("cp.async.cg.shared.global [%0], [%1], 16;"
                 :: "r"(dst), "l"(src) : "memory");
}
__device__ __forceinline__ void ldsm4(uint32_t* r, uint32_t addr) {
    asm volatile("ldmatrix.sync.aligned.m8n8.x4.shared.b16 {%0,%1,%2,%3}, [%4];"
                 : "=r"(r[0]), "=r"(r[1]), "=r"(r[2]), "=r"(r[3]) : "r"(addr));
}
__device__ __forceinline__ void mma16816(float* c, const uint32_t* a,
                                         const uint32_t* b) {
    asm volatile(
        "mma.sync.aligned.m16n8k16.row.col.f32.f16.f16.f32 "
        "{%0,%1,%2,%3}, {%4,%5,%6,%7}, {%8,%9}, {%0,%1,%2,%3};"
        : "+f"(c[0]), "+f"(c[1]), "+f"(c[2]), "+f"(c[3])
        : "r"(a[0]), "r"(a[1]), "r"(a[2]), "r"(a[3]), "r"(b[0]), "r"(b[1]));
}
__device__ __forceinline__ void split2h(float v, __half& h, __half& l) {
    h = __float2half_rn(v);
    l = __float2half_rn(v - __half2float(h));
}

// ---------------------------------------------------------------------------
// NT GEMM: C[M,N] = alpha * Ah[M,K] * B[N,K]^T
//   SPLITB=true : B = Bh + Bl (2 MMA passes)
//   SPLITB=false: B = Bh only (1 MMA pass)
// mode 0: fp32 out. mode 3: fp16 hi-only out.
// mode 4: fp16 hi-only TRANSPOSED out (Ch[col*Mrows + row]).
// Requires M mult 128, N mult 64, K mult 32.
// ---------------------------------------------------------------------------
template <bool SPLITB>
__global__ __launch_bounds__(128, 3)
void gemm_mma(const __half* __restrict__ Ah,
              const __half* __restrict__ Bh, const __half* __restrict__ Bl,
              float* __restrict__ Cf, __half* __restrict__ Ch,
              int Mrows, int Ncols, int Kdim, float alpha, int mode)
{
    extern __shared__ char dynraw[];
    const uint32_t sbase = s2u(dynraw);

    const int tid  = threadIdx.x;
    const int wid  = tid >> 5;
    const int lane = tid & 31;
    const int bx = blockIdx.x, by = blockIdx.y;

    const int wmBase = (wid & 1) * 64;      // warp M origin (0,64)
    const int wnBase = (wid >> 1) * 32;     // warp N origin (0,32)

    const size_t rowA0 = (size_t)by * BM;
    const size_t rowB0 = (size_t)bx * BN;

    auto load_chunk = [&](int kc, int stg) {
        const int k0 = kc * BKE;
        const uint32_t sb = sbase + stg * STAGE_B;
        #pragma unroll
        for (int i = 0; i < 4; i++) {                  // A: 512 x 16B
            const int idx = tid + i * 128;
            const int r = idx >> 2, c = idx & 3;
            const uint32_t so = (uint32_t)(r * RS * 2 + c * 16);
            cpa16(sb + OFF_A + so, Ah + (rowA0 + r) * (size_t)Kdim + k0 + c * 8);
        }
        #pragma unroll
        for (int i = 0; i < 2; i++) {                  // B: 256 x 16B each
            const int idx = tid + i * 128;
            const int r = idx >> 2, c = idx & 3;
            const uint32_t so = (uint32_t)(r * RS * 2 + c * 16);
            const size_t gb = (rowB0 + r) * (size_t)Kdim + k0 + c * 8;
            cpa16(sb + OFF_BH + so, Bh + gb);
            if (SPLITB) cpa16(sb + OFF_BL + so, Bl + gb);
        }
        asm volatile("cp.async.commit_group;" ::: "memory");
    };

    float acc[4][4][4];
    #pragma unroll
    for (int i = 0; i < 4; i++)
        #pragma unroll
        for (int j = 0; j < 4; j++)
            #pragma unroll
            for (int k = 0; k < 4; k++) acc[i][j][k] = 0.0f;

    const int nchunks = Kdim / BKE;

    const int q  = lane >> 3;
    const int r8 = lane & 7;
    const int aRowOff = ((q & 1) ? 8 : 0) + r8;
    const int aKOff   = ((q >> 1) ? 8 : 0);
    const int bRowOff = ((q >> 1) ? 8 : 0) + r8;
    const int bKOff   = ((q & 1) ? 8 : 0);

    // two fragment buffers: buf 0 <-> ks=0, buf 1 <-> ks=1
    uint32_t fa[2][4][4], fbh[2][2][4];
    uint32_t fbl[SPLITB ? 2 : 1][2][4];

    auto ldfrag = [&](int buf, uint32_t sb, int ks) {
        #pragma unroll
        for (int am = 0; am < 4; am++) {
            const uint32_t off =
                (uint32_t)((wmBase + am * 16 + aRowOff) * RS
                           + ks * 16 + aKOff) * 2;
            ldsm4(fa[buf][am], sb + OFF_A + off);
        }
        #pragma unroll
        for (int j = 0; j < 2; j++) {
            const uint32_t off =
                (uint32_t)((wnBase + j * 16 + bRowOff) * RS
                           + ks * 16 + bKOff) * 2;
            ldsm4(fbh[buf][j], sb + OFF_BH + off);
            if (SPLITB) ldsm4(fbl[buf][j], sb + OFF_BL + off);
        }
    };
    auto do_mma = [&](int buf) {
        #pragma unroll
        for (int j = 0; j < 2; j++)
            #pragma unroll
            for (int am = 0; am < 4; am++) {
                mma16816(acc[am][j * 2],     fa[buf][am], fbh[buf][j]);
                mma16816(acc[am][j * 2 + 1], fa[buf][am], fbh[buf][j] + 2);
            }
        if (SPLITB) {
            #pragma unroll
            for (int j = 0; j < 2; j++)
                #pragma unroll
                for (int am = 0; am < 4; am++) {
                    mma16816(acc[am][j * 2],     fa[buf][am], fbl[buf][j]);
                    mma16816(acc[am][j * 2 + 1], fa[buf][am], fbl[buf][j] + 2);
                }
        }
    };

    // prologue: stages 0,1 in flight; chunk 0 globally resident; frag ks0 in
    load_chunk(0, 0);
    if (nchunks > 1) {
        load_chunk(1, 1);
        asm volatile("cp.async.wait_group 1;" ::: "memory");  // own chunk0
    } else {
        asm volatile("cp.async.wait_group 0;" ::: "memory");
    }
    __syncthreads();                                            // ALL chunk0
    ldfrag(0, sbase, 0);

    // invariant at top of iter kc: chunk kc resident globally; buf0 = (kc,ks0)
    for (int kc = 0; kc < nchunks; kc++) {
        const uint32_t sb_cur = sbase + (kc % NSTAGE) * STAGE_B;
        const uint32_t sb_nxt = sbase + ((kc + 1) % NSTAGE) * STAGE_B;

        // phase A LDSM first — cheap work before the barrier, so warps
        // arrive with minimal skew; the MMA bursts then run unbroken.
        ldfrag(1, sb_cur, 1);

        // stage (kc+2)%3 == stage (kc-1): its last reader was iter kc-1's
        // phase-A ldfrag, which precedes iter kc-1's barrier -> safe.
        if (kc + 2 < nchunks) {
            load_chunk(kc + 2, (kc + 2) % NSTAGE);
            asm volatile("cp.async.wait_group 1;" ::: "memory"); // kc+1 own-done
        } else {
            asm volatile("cp.async.wait_group 0;" ::: "memory");
        }
        __syncthreads();   // chunk kc+1 resident for ALL warps

        // one long compute run: MMA(ks0) | LDSM(kc+1,ks0) | MMA(ks1)
        do_mma(0);
        if (kc + 1 < nchunks) ldfrag(0, sb_nxt, 0);
        do_mma(1);
    }

    // ---------------- epilogue --------------------------------------------
    #pragma unroll
    for (int am = 0; am < 4; am++) {
        const int r0 = by * BM + wmBase + am * 16 + (lane >> 2);
        #pragma unroll
        for (int an = 0; an < 4; an++) {
            const int c0 = bx * BN + wnBase + an * 8 + (lane & 3) * 2;
            const float v00 = alpha * acc[am][an][0];
            const float v01 = alpha * acc[am][an][1];
            const float v10 = alpha * acc[am][an][2];
            const float v11 = alpha * acc[am][an][3];
            if (mode == 0) {
                *(float2*)(Cf + (size_t)r0 * Ncols + c0)       = make_float2(v00, v01);
                *(float2*)(Cf + (size_t)(r0 + 8) * Ncols + c0) = make_float2(v10, v11);
            } else if (mode == 3) {          // fp16 hi only, row-major
                *(__half2*)(Ch + (size_t)r0 * Ncols + c0) =
                    __halves2half2(__float2half_rn(v00), __float2half_rn(v01));
                *(__half2*)(Ch + (size_t)(r0 + 8) * Ncols + c0) =
                    __halves2half2(__float2half_rn(v10), __float2half_rn(v11));
            } else {                         // mode 4: fp16 hi only, transposed
                Ch[(size_t)c0 * Mrows + r0]           = __float2half_rn(v00);
                Ch[(size_t)(c0 + 1) * Mrows + r0]     = __float2half_rn(v01);
                Ch[(size_t)c0 * Mrows + r0 + 8]       = __float2half_rn(v10);
                Ch[(size_t)(c0 + 1) * Mrows + r0 + 8] = __float2half_rn(v11);
            }
        }
    }
}

// ---------------------------------------------------------------------------
// fp32 -> fp16 cast (A-side tensors)
// ---------------------------------------------------------------------------
__global__ __launch_bounds__(256)
void cast_f32_f16(const float* __restrict__ x, __half* __restrict__ h, size_t n)
{
    size_t i = (size_t)blockIdx.x * 256 + threadIdx.x;
    size_t stride = (size_t)gridDim.x * 256;
    for (; i < n; i += stride) h[i] = __float2half_rn(x[i]);
}

// fused conversions of the four MFxMF weight matrices:
// Wk,Wq,Wv split (hi,lo); Wo hi-only.
__global__ __launch_bounds__(256)
void split_w4(const float* __restrict__ w0, __half* __restrict__ h0, __half* __restrict__ l0,
              const float* __restrict__ w1, __half* __restrict__ h1, __half* __restrict__ l1,
              const float* __restrict__ w2, __half* __restrict__ h2, __half* __restrict__ l2,
              const float* __restrict__ w3, __half* __restrict__ h3)
{
    const size_t n = (size_t)MF * MF;
    size_t i = (size_t)blockIdx.x * 256 + threadIdx.x;
    size_t stride = (size_t)gridDim.x * 256;
    for (; i < n; i += stride) {
        float v; __half hb, lb;
        v = w0[i]; split2h(v, hb, lb); h0[i] = hb; l0[i] = lb;
        v = w1[i]; split2h(v, hb, lb); h1[i] = hb; l1[i] = lb;
        v = w2[i]; split2h(v, hb, lb); h2[i] = hb; l2[i] = lb;
        h3[i] = __float2half_rn(w3[i]);
    }
}

// ---------------------------------------------------------------------------
// Row softmax + dropout mask -> fp16  (MUST run with SMX_T threads)
// ---------------------------------------------------------------------------
#define SMX_T 512
__global__ __launch_bounds__(SMX_T)
void softmax_dropout_h(const float* __restrict__ S, const float* __restrict__ u,
                       __half* __restrict__ Sh)
{
    __shared__ float row[NF];
    __shared__ float red[SMX_T];

    const int r = blockIdx.x;
    const int tid = threadIdx.x;
    const float* Srow = S + (size_t)r * NF;
    const float* urow = u + (size_t)r * NF;
    const size_t base = (size_t)r * NF;

    float lmax = -INFINITY;
    for (int c = tid; c < NF; c += SMX_T) {
        float v = Srow[c];
        row[c] = v;
        lmax = fmaxf(lmax, v);
    }
    red[tid] = lmax;
    __syncthreads();
    #pragma unroll
    for (int s = SMX_T / 2; s > 0; s >>= 1) {
        if (tid < s) red[tid] = fmaxf(red[tid], red[tid + s]);
        __syncthreads();
    }
    const float m = red[0];
    __syncthreads();

    float lsum = 0.0f;
    for (int c = tid; c < NF; c += SMX_T) {
        float e = __expf(row[c] - m);
        row[c] = e;
        lsum += e;
    }
    red[tid] = lsum;
    __syncthreads();
    #pragma unroll
    for (int s = SMX_T / 2; s > 0; s >>= 1) {
        if (tid < s) red[tid] += red[tid + s];
        __syncthreads();
    }
    const float inv = 1.0f / red[0];

    for (int c = tid; c < NF; c += SMX_T) {
        float keep = (urow[c] >= 0.5f) ? 2.0f : 0.0f;
        Sh[base + c] = __float2half_rn(row[c] * inv * keep);
    }
}

// ---------------------------------------------------------------------------
// Launch
// ---------------------------------------------------------------------------
extern "C" void kernel_launch(void* const* d_in, const int* in_sizes, int n_in,
                              void* d_out, int out_size)
{
    const float* x  = (const float*)d_in[0];
    const float* Wk = (const float*)d_in[1];
    const float* Wq = (const float*)d_in[2];
    const float* Wv = (const float*)d_in[3];
    const float* Wo = (const float*)d_in[4];
    const float* u  = (const float*)d_in[5];
    float* out = (float*)d_out;

    cudaFuncSetAttribute(gemm_mma<true>,
                         cudaFuncAttributeMaxDynamicSharedMemorySize, DYN_SMEM);
    cudaFuncSetAttribute(gemm_mma<false>,
                         cudaFuncAttributeMaxDynamicSharedMemorySize, DYN_SMEM);

    float* S;
    __half *xh, *Wkh, *Wkl, *Wqh, *Wql, *Wvh, *Wvl, *Woh;
    __half *Kh, *Qh, *Vth, *Sh, *Yh;
    cudaGetSymbolAddress((void**)&S, g_S);
    cudaGetSymbolAddress((void**)&xh, g_xh);
    cudaGetSymbolAddress((void**)&Wkh, g_Wkh); cudaGetSymbolAddress((void**)&Wkl, g_Wkl);
    cudaGetSymbolAddress((void**)&Wqh, g_Wqh); cudaGetSymbolAddress((void**)&Wql, g_Wql);
    cudaGetSymbolAddress((void**)&Wvh, g_Wvh); cudaGetSymbolAddress((void**)&Wvl, g_Wvl);
    cudaGetSymbolAddress((void**)&Woh, g_Woh);
    cudaGetSymbolAddress((void**)&Kh, g_Kh);
    cudaGetSymbolAddress((void**)&Qh, g_Qh);
    cudaGetSymbolAddress((void**)&Vth, g_Vth);
    cudaGetSymbolAddress((void**)&Sh, g_Sh);
    cudaGetSymbolAddress((void**)&Yh, g_Yh);

    // 1) conversions
    cast_f32_f16<<<4096, 256>>>(x, xh, (size_t)NF * MF);             // launch 0
    split_w4<<<1024, 256>>>(Wk, Wkh, Wkl, Wq, Wqh, Wql,
                            Wv, Wvh, Wvl, Wo, Woh);                  // launch 1

    const dim3 gemmBlk(128);
    const dim3 gProj(MF / BN, NF / BM);   // (16, 64)
    const dim3 gAttn(NF / BN, NF / BM);   // (128, 64)

    // 2) projections (2-pass inputs; hi-only outputs)
    gemm_mma<true><<<gProj, gemmBlk, DYN_SMEM>>>(xh, Wkh, Wkl, nullptr, Kh,
                                                 NF, MF, MF, 1.0f, 3);
    gemm_mma<true><<<gProj, gemmBlk, DYN_SMEM>>>(xh, Wqh, Wql, nullptr, Qh,
                                                 NF, MF, MF, 0.06f, 3);
    gemm_mma<true><<<gProj, gemmBlk, DYN_SMEM>>>(xh, Wvh, Wvl, nullptr, Vth,
                                                 NF, MF, MF, 1.0f, 4);

    // 3) logits S = Q K^T (fp32), single-pass — launch 5 for ncu
    gemm_mma<false><<<gAttn, gemmBlk, DYN_SMEM>>>(Qh, Kh, nullptr, S, nullptr,
                                                  NF, NF, MF, 1.0f, 0);

    // 4) softmax + dropout -> fp16
    softmax_dropout_h<<<NF, SMX_T>>>(S, u, Sh);

    // 5) Y = W V — single-pass
    gemm_mma<false><<<gProj, gemmBlk, DYN_SMEM>>>(Sh, Vth, nullptr, nullptr, Yh,
                                                  NF, MF, NF, 1.0f, 3);

    // 6) out = Y Wo^T (fp32) — single-pass (Wol dropped; last precision cut)
    gemm_mma<false><<<gProj, gemmBlk, DYN_SMEM>>>(Yh, Woh, nullptr, out, nullptr,
                                                  NF, MF, MF, 1.0f, 0);
}

// round 17
// speedup vs baseline: 1.1037x; 1.1037x over previous
#include <cuda_runtime.h>
#include <cuda_fp16.h>
#include <cstdint>
#include <math.h>

// ---------------------------------------------------------------------------
// SelfAttention via split-fp16 HMMA (mma.sync m16n8k16.f32.f16.f16.f32).
// out = softmax((x Wq^T * 0.06)(x Wk^T)^T)*dropmask @ (x Wv^T) @ Wo^T
// N = 8192, M = 1024.
// Precision scheme (calibrated R8..R16, measured rel_err 4.88e-4):
//   - A operands always fp16 hi-only.
//   - Projections (Wk,Wq,Wv): B split hi+lo, 2 passes (must stay split).
//   - QK^T, S@V, out GEMM: single-pass.
// R17 = R15 mainloop ordering (the R16 barrier reorder regressed single-pass
//       GEMMs by removing the commit->wait MMA slack) + single-pass out GEMM
//       (the one R16 piece that worked) + 256-thread softmax (reverted).
// ---------------------------------------------------------------------------

#define NF 8192
#define MF 1024

// ---------------- scratch (__device__ globals) ------------------------------
__device__ float  g_S [(size_t)NF * NF];                 // 256 MB logits
__device__ __half g_Sh[(size_t)NF * NF];                 // 128 MB (A side)
__device__ __half g_xh[(size_t)NF * MF];
__device__ __half g_Wkh[(size_t)MF * MF], g_Wkl[(size_t)MF * MF];
__device__ __half g_Wqh[(size_t)MF * MF], g_Wql[(size_t)MF * MF];
__device__ __half g_Wvh[(size_t)MF * MF], g_Wvl[(size_t)MF * MF];
__device__ __half g_Woh[(size_t)MF * MF];                // Wo hi only
__device__ __half g_Kh[(size_t)NF * MF];                 // K hi only
__device__ __half g_Qh[(size_t)NF * MF];
__device__ __half g_Vth[(size_t)MF * NF];                // V^T hi only
__device__ __half g_Yh[(size_t)NF * MF];

// ---------------- tile config ----------------------------------------------
#define BM 128
#define BN 64
#define BKE 32                    // K elems per chunk (fp16)
#define RS 40                     // smem row stride in elems (80 B)
#define OFF_A  0                          // A: 128 rows x 80B = 10240
#define OFF_BH (BM * RS * 2)              // Bh: 64 rows x 80B = 5120
#define OFF_BL (BM * RS * 2 + BN * RS * 2)
#define STAGE_B ((BM + 2 * BN) * RS * 2)  // 20480
#define NSTAGE 3
#define DYN_SMEM (NSTAGE * STAGE_B)       // 61440/CTA (3 CTAs -> 180 KB/SM)

// ---------------- PTX helpers ----------------------------------------------
__device__ __forceinline__ uint32_t s2u(const void* p) {
    uint32_t a;
    asm("{ .reg .u64 t; cvta.to.shared.u64 t, %1; cvt.u32.u64 %0, t; }"
        : "=r"(a) : "l"(p));
    return a;
}
__device__ __forceinline__ void cpa16(uint32_t dst, const void* src) {
    asm volatile("cp.async.cg.shared.global [%0], [%1], 16;"
                 :: "r"(dst), "l"(src) : "memory");
}
__device__ __forceinline__ void ldsm4(uint32_t* r, uint32_t addr) {
    asm volatile("ldmatrix.sync.aligned.m8n8.x4.shared.b16 {%0,%1,%2,%3}, [%4];"
                 : "=r"(r[0]), "=r"(r[1]), "=r"(r[2]), "=r"(r[3]) : "r"(addr));
}
__device__ __forceinline__ void mma16816(float* c, const uint32_t* a,
                                         const uint32_t* b) {
    asm volatile(
        "mma.sync.aligned.m16n8k16.row.col.f32.f16.f16.f32 "
        "{%0,%1,%2,%3}, {%4,%5,%6,%7}, {%8,%9}, {%0,%1,%2,%3};"
        : "+f"(c[0]), "+f"(c[1]), "+f"(c[2]), "+f"(c[3])
        : "r"(a[0]), "r"(a[1]), "r"(a[2]), "r"(a[3]), "r"(b[0]), "r"(b[1]));
}
__device__ __forceinline__ void split2h(float v, __half& h, __half& l) {
    h = __float2half_rn(v);
    l = __float2half_rn(v - __half2float(h));
}

// ---------------------------------------------------------------------------
// NT GEMM: C[M,N] = alpha * Ah[M,K] * B[N,K]^T
//   SPLITB=true : B = Bh + Bl (2 MMA passes)
//   SPLITB=false: B = Bh only (1 MMA pass)
// mode 0: fp32 out. mode 3: fp16 hi-only out.
// mode 4: fp16 hi-only TRANSPOSED out (Ch[col*Mrows + row]).
// Requires M mult 128, N mult 64, K mult 32.
// ---------------------------------------------------------------------------
template <bool SPLITB>
__global__ __launch_bounds__(128, 3)
void gemm_mma(const __half* __restrict__ Ah,
              const __half* __restrict__ Bh, const __half* __restrict__ Bl,
              float* __restrict__ Cf, __half* __restrict__ Ch,
              int Mrows, int Ncols, int Kdim, float alpha, int mode)
{
    extern __shared__ char dynraw[];
    const uint32_t sbase = s2u(dynraw);

    const int tid  = threadIdx.x;
    const int wid  = tid >> 5;
    const int lane = tid & 31;
    const int bx = blockIdx.x, by = blockIdx.y;

    const int wmBase = (wid & 1) * 64;      // warp M origin (0,64)
    const int wnBase = (wid >> 1) * 32;     // warp N origin (0,32)

    const size_t rowA0 = (size_t)by * BM;
    const size_t rowB0 = (size_t)bx * BN;

    auto load_chunk = [&](int kc, int stg) {
        const int k0 = kc * BKE;
        const uint32_t sb = sbase + stg * STAGE_B;
        #pragma unroll
        for (int i = 0; i < 4; i++) {                  // A: 512 x 16B
            const int idx = tid + i * 128;
            const int r = idx >> 2, c = idx & 3;
            const uint32_t so = (uint32_t)(r * RS * 2 + c * 16);
            cpa16(sb + OFF_A + so, Ah + (rowA0 + r) * (size_t)Kdim + k0 + c * 8);
        }
        #pragma unroll
        for (int i = 0; i < 2; i++) {                  // B: 256 x 16B each
            const int idx = tid + i * 128;
            const int r = idx >> 2, c = idx & 3;
            const uint32_t so = (uint32_t)(r * RS * 2 + c * 16);
            const size_t gb = (rowB0 + r) * (size_t)Kdim + k0 + c * 8;
            cpa16(sb + OFF_BH + so, Bh + gb);
            if (SPLITB) cpa16(sb + OFF_BL + so, Bl + gb);
        }
        asm volatile("cp.async.commit_group;" ::: "memory");
    };

    float acc[4][4][4];
    #pragma unroll
    for (int i = 0; i < 4; i++)
        #pragma unroll
        for (int j = 0; j < 4; j++)
            #pragma unroll
            for (int k = 0; k < 4; k++) acc[i][j][k] = 0.0f;

    const int nchunks = Kdim / BKE;

    const int q  = lane >> 3;
    const int r8 = lane & 7;
    const int aRowOff = ((q & 1) ? 8 : 0) + r8;
    const int aKOff   = ((q >> 1) ? 8 : 0);
    const int bRowOff = ((q >> 1) ? 8 : 0) + r8;
    const int bKOff   = ((q & 1) ? 8 : 0);

    // two fragment buffers: buf 0 <-> ks=0, buf 1 <-> ks=1
    uint32_t fa[2][4][4], fbh[2][2][4];
    uint32_t fbl[SPLITB ? 2 : 1][2][4];

    auto ldfrag = [&](int buf, uint32_t sb, int ks) {
        #pragma unroll
        for (int am = 0; am < 4; am++) {
            const uint32_t off =
                (uint32_t)((wmBase + am * 16 + aRowOff) * RS
                           + ks * 16 + aKOff) * 2;
            ldsm4(fa[buf][am], sb + OFF_A + off);
        }
        #pragma unroll
        for (int j = 0; j < 2; j++) {
            const uint32_t off =
                (uint32_t)((wnBase + j * 16 + bRowOff) * RS
                           + ks * 16 + bKOff) * 2;
            ldsm4(fbh[buf][j], sb + OFF_BH + off);
            if (SPLITB) ldsm4(fbl[buf][j], sb + OFF_BL + off);
        }
    };
    auto do_mma = [&](int buf) {
        #pragma unroll
        for (int j = 0; j < 2; j++)
            #pragma unroll
            for (int am = 0; am < 4; am++) {
                mma16816(acc[am][j * 2],     fa[buf][am], fbh[buf][j]);
                mma16816(acc[am][j * 2 + 1], fa[buf][am], fbh[buf][j] + 2);
            }
        if (SPLITB) {
            #pragma unroll
            for (int j = 0; j < 2; j++)
                #pragma unroll
                for (int am = 0; am < 4; am++) {
                    mma16816(acc[am][j * 2],     fa[buf][am], fbl[buf][j]);
                    mma16816(acc[am][j * 2 + 1], fa[buf][am], fbl[buf][j] + 2);
                }
        }
    };

    // prologue: stages 0,1 in flight; chunk 0 globally resident; frag ks0 in
    load_chunk(0, 0);
    if (nchunks > 1) {
        load_chunk(1, 1);
        asm volatile("cp.async.wait_group 1;" ::: "memory");  // own chunk0
    } else {
        asm volatile("cp.async.wait_group 0;" ::: "memory");
    }
    __syncthreads();                                            // ALL chunk0
    ldfrag(0, sbase, 0);

    // invariant at top of iter kc: chunk kc resident globally; buf0 = (kc,ks0)
    // R15 ordering: the commit->wait window contains do_mma(0), giving the
    // in-flight cp.async a full MMA burst of slack before any warp waits.
    for (int kc = 0; kc < nchunks; kc++) {
        const uint32_t sb_cur = sbase + (kc % NSTAGE) * STAGE_B;
        const uint32_t sb_nxt = sbase + ((kc + 1) % NSTAGE) * STAGE_B;

        // phase A: prefetch (kc, ks1) under MMA of (kc, ks0)
        ldfrag(1, sb_cur, 1);
        do_mma(0);

        if (kc + 2 < nchunks) {
            load_chunk(kc + 2, (kc + 2) % NSTAGE);
            asm volatile("cp.async.wait_group 1;" ::: "memory");
        } else {
            asm volatile("cp.async.wait_group 0;" ::: "memory");
        }
        __syncthreads();   // chunk kc+1 resident for ALL warps

        // phase B: prefetch (kc+1, ks0) under MMA of (kc, ks1)
        if (kc + 1 < nchunks) ldfrag(0, sb_nxt, 0);
        do_mma(1);
    }

    // ---------------- epilogue --------------------------------------------
    #pragma unroll
    for (int am = 0; am < 4; am++) {
        const int r0 = by * BM + wmBase + am * 16 + (lane >> 2);
        #pragma unroll
        for (int an = 0; an < 4; an++) {
            const int c0 = bx * BN + wnBase + an * 8 + (lane & 3) * 2;
            const float v00 = alpha * acc[am][an][0];
            const float v01 = alpha * acc[am][an][1];
            const float v10 = alpha * acc[am][an][2];
            const float v11 = alpha * acc[am][an][3];
            if (mode == 0) {
                *(float2*)(Cf + (size_t)r0 * Ncols + c0)       = make_float2(v00, v01);
                *(float2*)(Cf + (size_t)(r0 + 8) * Ncols + c0) = make_float2(v10, v11);
            } else if (mode == 3) {          // fp16 hi only, row-major
                *(__half2*)(Ch + (size_t)r0 * Ncols + c0) =
                    __halves2half2(__float2half_rn(v00), __float2half_rn(v01));
                *(__half2*)(Ch + (size_t)(r0 + 8) * Ncols + c0) =
                    __halves2half2(__float2half_rn(v10), __float2half_rn(v11));
            } else {                         // mode 4: fp16 hi only, transposed
                Ch[(size_t)c0 * Mrows + r0]           = __float2half_rn(v00);
                Ch[(size_t)(c0 + 1) * Mrows + r0]     = __float2half_rn(v01);
                Ch[(size_t)c0 * Mrows + r0 + 8]       = __float2half_rn(v10);
                Ch[(size_t)(c0 + 1) * Mrows + r0 + 8] = __float2half_rn(v11);
            }
        }
    }
}

// ---------------------------------------------------------------------------
// fp32 -> fp16 cast (A-side tensors)
// ---------------------------------------------------------------------------
__global__ __launch_bounds__(256)
void cast_f32_f16(const float* __restrict__ x, __half* __restrict__ h, size_t n)
{
    size_t i = (size_t)blockIdx.x * 256 + threadIdx.x;
    size_t stride = (size_t)gridDim.x * 256;
    for (; i < n; i += stride) h[i] = __float2half_rn(x[i]);
}

// fused conversions: Wk,Wq,Wv split (hi,lo); Wo hi-only.
__global__ __launch_bounds__(256)
void split_w4(const float* __restrict__ w0, __half* __restrict__ h0, __half* __restrict__ l0,
              const float* __restrict__ w1, __half* __restrict__ h1, __half* __restrict__ l1,
              const float* __restrict__ w2, __half* __restrict__ h2, __half* __restrict__ l2,
              const float* __restrict__ w3, __half* __restrict__ h3)
{
    const size_t n = (size_t)MF * MF;
    size_t i = (size_t)blockIdx.x * 256 + threadIdx.x;
    size_t stride = (size_t)gridDim.x * 256;
    for (; i < n; i += stride) {
        float v; __half hb, lb;
        v = w0[i]; split2h(v, hb, lb); h0[i] = hb; l0[i] = lb;
        v = w1[i]; split2h(v, hb, lb); h1[i] = hb; l1[i] = lb;
        v = w2[i]; split2h(v, hb, lb); h2[i] = hb; l2[i] = lb;
        h3[i] = __float2half_rn(w3[i]);
    }
}

// ---------------------------------------------------------------------------
// Row softmax + dropout mask -> fp16  (MUST run with SMX_T threads)
// ---------------------------------------------------------------------------
#define SMX_T 256
__global__ __launch_bounds__(SMX_T)
void softmax_dropout_h(const float* __restrict__ S, const float* __restrict__ u,
                       __half* __restrict__ Sh)
{
    __shared__ float row[NF];
    __shared__ float red[SMX_T];

    const int r = blockIdx.x;
    const int tid = threadIdx.x;
    const float* Srow = S + (size_t)r * NF;
    const float* urow = u + (size_t)r * NF;
    const size_t base = (size_t)r * NF;

    float lmax = -INFINITY;
    for (int c = tid; c < NF; c += SMX_T) {
        float v = Srow[c];
        row[c] = v;
        lmax = fmaxf(lmax, v);
    }
    red[tid] = lmax;
    __syncthreads();
    #pragma unroll
    for (int s = SMX_T / 2; s > 0; s >>= 1) {
        if (tid < s) red[tid] = fmaxf(red[tid], red[tid + s]);
        __syncthreads();
    }
    const float m = red[0];
    __syncthreads();

    float lsum = 0.0f;
    for (int c = tid; c < NF; c += SMX_T) {
        float e = __expf(row[c] - m);
        row[c] = e;
        lsum += e;
    }
    red[tid] = lsum;
    __syncthreads();
    #pragma unroll
    for (int s = SMX_T / 2; s > 0; s >>= 1) {
        if (tid < s) red[tid] += red[tid + s];
        __syncthreads();
    }
    const float inv = 1.0f / red[0];

    for (int c = tid; c < NF; c += SMX_T) {
        float keep = (urow[c] >= 0.5f) ? 2.0f : 0.0f;
        Sh[base + c] = __float2half_rn(row[c] * inv * keep);
    }
}

// ---------------------------------------------------------------------------
// Launch
// ---------------------------------------------------------------------------
extern "C" void kernel_launch(void* const* d_in, const int* in_sizes, int n_in,
                              void* d_out, int out_size)
{
    const float* x  = (const float*)d_in[0];
    const float* Wk = (const float*)d_in[1];
    const float* Wq = (const float*)d_in[2];
    const float* Wv = (const float*)d_in[3];
    const float* Wo = (const float*)d_in[4];
    const float* u  = (const float*)d_in[5];
    float* out = (float*)d_out;

    cudaFuncSetAttribute(gemm_mma<true>,
                         cudaFuncAttributeMaxDynamicSharedMemorySize, DYN_SMEM);
    cudaFuncSetAttribute(gemm_mma<false>,
                         cudaFuncAttributeMaxDynamicSharedMemorySize, DYN_SMEM);

    float* S;
    __half *xh, *Wkh, *Wkl, *Wqh, *Wql, *Wvh, *Wvl, *Woh;
    __half *Kh, *Qh, *Vth, *Sh, *Yh;
    cudaGetSymbolAddress((void**)&S, g_S);
    cudaGetSymbolAddress((void**)&xh, g_xh);
    cudaGetSymbolAddress((void**)&Wkh, g_Wkh); cudaGetSymbolAddress((void**)&Wkl, g_Wkl);
    cudaGetSymbolAddress((void**)&Wqh, g_Wqh); cudaGetSymbolAddress((void**)&Wql, g_Wql);
    cudaGetSymbolAddress((void**)&Wvh, g_Wvh); cudaGetSymbolAddress((void**)&Wvl, g_Wvl);
    cudaGetSymbolAddress((void**)&Woh, g_Woh);
    cudaGetSymbolAddress((void**)&Kh, g_Kh);
    cudaGetSymbolAddress((void**)&Qh, g_Qh);
    cudaGetSymbolAddress((void**)&Vth, g_Vth);
    cudaGetSymbolAddress((void**)&Sh, g_Sh);
    cudaGetSymbolAddress((void**)&Yh, g_Yh);

    // 1) conversions
    cast_f32_f16<<<4096, 256>>>(x, xh, (size_t)NF * MF);             // launch 0
    split_w4<<<1024, 256>>>(Wk, Wkh, Wkl, Wq, Wqh, Wql,
                            Wv, Wvh, Wvl, Wo, Woh);                  // launch 1

    const dim3 gemmBlk(128);
    const dim3 gProj(MF / BN, NF / BM);   // (16, 64)
    const dim3 gAttn(NF / BN, NF / BM);   // (128, 64)

    // 2) projections (2-pass inputs; hi-only outputs)
    gemm_mma<true><<<gProj, gemmBlk, DYN_SMEM>>>(xh, Wkh, Wkl, nullptr, Kh,
                                                 NF, MF, MF, 1.0f, 3);
    gemm_mma<true><<<gProj, gemmBlk, DYN_SMEM>>>(xh, Wqh, Wql, nullptr, Qh,
                                                 NF, MF, MF, 0.06f, 3);
    gemm_mma<true><<<gProj, gemmBlk, DYN_SMEM>>>(xh, Wvh, Wvl, nullptr, Vth,
                                                 NF, MF, MF, 1.0f, 4);

    // 3) logits S = Q K^T (fp32), single-pass
    gemm_mma<false><<<gAttn, gemmBlk, DYN_SMEM>>>(Qh, Kh, nullptr, S, nullptr,
                                                  NF, NF, MF, 1.0f, 0);

    // 4) softmax + dropout -> fp16
    softmax_dropout_h<<<NF, SMX_T>>>(S, u, Sh);

    // 5) Y = W V — single-pass
    gemm_mma<false><<<gProj, gemmBlk, DYN_SMEM>>>(Sh, Vth, nullptr, nullptr, Yh,
                                                  NF, MF, NF, 1.0f, 3);

    // 6) out = Y Wo^T (fp32) — single-pass
    gemm_mma<false><<<gProj, gemmBlk, DYN_SMEM>>>(Yh, Woh, nullptr, out, nullptr,
                                                  NF, MF, MF, 1.0f, 0);
}